// round 9
// baseline (speedup 1.0000x reference)
#include <cuda_runtime.h>

#define Nn 5000
#define Ee 80000
#define FIN 32
#define Dd 64
#define P1n 256
#define P2n 32
#define Hh 256
#define Mm 5288
#define ELLW 64
#define SCALE 1.4763057f
#define M1 (256.f/5000.f)

typedef unsigned long long u64;

// ---------------- packed f32x2 helpers ----------------
__device__ __forceinline__ void fma2(u64& acc, u64 b, u64 a) {
    asm("fma.rn.f32x2 %0, %1, %2, %0;" : "+l"(acc) : "l"(b), "l"(a));
}
__device__ __forceinline__ u64 pk2(float lo, float hi) {
    u64 r; asm("mov.b64 %0, {%1, %2};" : "=l"(r) : "f"(lo), "f"(hi)); return r;
}
__device__ __forceinline__ void unpk(u64 v, float& a, float& b) {
    asm("mov.b64 {%0, %1}, %2;" : "=f"(a), "=f"(b) : "l"(v));
}
__device__ __forceinline__ float sum2(u64 v) {
    float a, b; unpk(v, a, b); return a + b;
}
__device__ __forceinline__ void red4(float* p, float a, float b, float c, float d) {
    asm volatile("red.global.add.v4.f32 [%0], {%1,%2,%3,%4};"
                 :: "l"(p), "f"(a), "f"(b), "f"(c), "f"(d) : "memory");
}

// ---------------- scratch (static, no allocation) ----------------
__device__ __align__(16) float g_z[Nn * Dd];
__device__ __align__(16) float g_XW1[Nn * Dd];
__device__ __align__(16) float g_E1[Nn * P1n];   // exp(P1) unnormalized
__device__ __align__(16) float g_AS1[Nn * P1n];  // A @ E1 (unscaled)
__device__ __align__(16) float g_ze1[Nn * Dd];
__device__ __align__(16) float g_U[5056 * Dd];   // AS1 @ (D_iz x1)
__device__ int g_cnt[Nn];
__device__ int g_ell[Nn * ELLW];
__device__ float g_colE[P1n], g_colEV[P1n], g_invZ[P1n];
__device__ __align__(16) float g_x1[P1n * Dd];
__device__ float g_y1[P1n];
__device__ __align__(16) float g_V[P1n * Dd];    // E1^T U (unscaled)
__device__ __align__(16) float g_S2[P1n * P2n];
__device__ __align__(16) float g_ze2[P1n * Dd];
__device__ float g_c[Hh], g_q[Hh], g_w0[Hh];
__device__ float g_acc[4];   // [0]=ent, [1]=sum(u-y)^2, [2]=sum(res^2)

// ---------------- kernel: zero accumulators + decoder prep ----------------
__global__ void prep(const float* __restrict__ t, const float* __restrict__ W1,
                     const float* __restrict__ b1) {
    int i = blockIdx.x * blockDim.x + threadIdx.x;
    int st = gridDim.x * blockDim.x;
    for (int k = i; k < Nn; k += st) g_cnt[k] = 0;
    for (int k = i; k < P1n; k += st) { g_colE[k] = 0.f; g_colEV[k] = 0.f; g_y1[k] = 0.f; }
    for (int k = i; k < P1n * Dd; k += st) { g_x1[k] = 0.f; g_V[k] = 0.f; }
    if (i == 0) { g_acc[0] = g_acc[1] = g_acc[2] = g_acc[3] = 0.f; }
    if (blockIdx.x == 0) {
        int h = threadIdx.x;
        float t0 = t[0];
        float tx[6];
        tx[0] = t0 * 1e-2f;
        tx[1] = t0 * 1e-3f;
        tx[2] = t0 * 1e-4f;
        tx[3] = logf(t0 * 100.f + 1.f);
        tx[4] = logf(t0 * 10.f + 1.f);
        tx[5] = logf(t0 + 1.f);
        float c = b1[h];
#pragma unroll
        for (int k = 0; k < 6; k++) c += W1[k * Hh + h] * tx[k];
        float q = 0.f;
#pragma unroll
        for (int k = 1; k < 9; k++) { float w = W1[k * Hh + h]; q += w * w; }
        g_c[h] = c; g_q[h] = q; g_w0[h] = W1[h];
    }
}

// ---------------- kernel: edge ELL scatter ----------------
__global__ void edge_build(const int* __restrict__ adj) {
    int e = blockIdx.x * blockDim.x + threadIdx.x;
    if (e >= Ee) return;
    int r0 = adj[e], r1 = adj[Ee + e];
    int pos = atomicAdd(&g_cnt[r0], 1);
    if (pos < ELLW) g_ell[r0 * ELLW + pos] = r1;
}

// ---------------- kernel: encode + XW1 + exp(P1) + column sums ----------------
__global__ void __launch_bounds__(256) encodeK(
    const float* __restrict__ x0, const float* __restrict__ Wenc,
    const float* __restrict__ Wemb, const float* __restrict__ Wp) {
    int tid = threadIdx.x;
    __shared__ float xsh[32][FIN];
    __shared__ __align__(16) float zsh[32][Dd];
    int r0 = blockIdx.x * 32;
    for (int idx = tid; idx < 32 * FIN; idx += 256) {
        int r = idx / FIN, c = idx % FIN;
        int row = r0 + r;
        xsh[r][c] = (row < Nn) ? x0[row * FIN + c] : 0.f;
    }
    __syncthreads();
    for (int idx = tid; idx < 32 * Dd; idx += 256) {
        int r = idx / Dd, d = idx % Dd;
        float a = 0.f;
#pragma unroll
        for (int k = 0; k < FIN; k++) a += xsh[r][k] * Wenc[k * (Dd + 3) + d];
        float v = tanhf(a) * SCALE;
        zsh[r][d] = v;
        int row = r0 + r;
        if (row < Nn) g_z[row * Dd + d] = v;
    }
    __syncthreads();
    for (int idx = tid; idx < 32 * Dd; idx += 256) {
        int r = idx / Dd, d = idx % Dd;
        int row = r0 + r;
        if (row < Nn) {
            float a = 0.f;
#pragma unroll
            for (int k = 0; k < Dd; k++) a += zsh[r][k] * Wemb[k * Dd + d];
            g_XW1[row * Dd + d] = a;
        }
    }
    int p = tid;
    u64 wp[32];
#pragma unroll
    for (int kk = 0; kk < 32; kk++)
        wp[kk] = pk2(Wp[(2 * kk) * P1n + p], Wp[(2 * kk + 1) * P1n + p]);
    float se = 0.f, sev = 0.f;
    int rmax = Nn - r0; if (rmax > 32) rmax = 32;
    for (int r = 0; r < rmax; r++) {
        u64 acc = 0ull;
        const ulonglong2* zz = (const ulonglong2*)zsh[r];
#pragma unroll
        for (int q = 0; q < 16; q++) {
            ulonglong2 zp = zz[q];
            fma2(acc, zp.x, wp[2 * q]);
            fma2(acc, zp.y, wp[2 * q + 1]);
        }
        float v = sum2(acc) * SCALE;
        float e = __expf(v);
        g_E1[(r0 + r) * P1n + p] = e;
        se += e; sev += e * v;
    }
    atomicAdd(&g_colE[p], se);
    atomicAdd(&g_colEV[p], sev);
}

// ---------------- kernel: per-row dedup + sparse gathers + finalize ----------------
__global__ void __launch_bounds__(256) gather_fused() {
    if (blockIdx.x == 1250) {
        int p = threadIdx.x;
        float Z = g_colE[p];
        float iz = 1.f / Z;
        g_invZ[p] = iz;
        float ent = __logf(Z) - g_colEV[p] * iz;
        __shared__ float sh[8];
#pragma unroll
        for (int off = 16; off; off >>= 1) ent += __shfl_down_sync(0xffffffffu, ent, off);
        if ((p & 31) == 0) sh[p >> 5] = ent;
        __syncthreads();
        if (p == 0) {
            float s = 0.f;
            for (int w = 0; w < 8; w++) s += sh[w];
            atomicAdd(&g_acc[0], s * (1.f / ((float)Nn * (float)P1n)));
        }
        return;
    }
    int g = threadIdx.x >> 7;
    int l = threadIdx.x & 127;
    __shared__ int cls[2][ELLW];
    __shared__ int scn[2];
    __shared__ int sdup[2];
#pragma unroll
    for (int rr = 0; rr < 2; rr++) {
        int i = blockIdx.x * 4 + g * 2 + rr;
        int cn = g_cnt[i]; if (cn > ELLW) cn = ELLW;
        __syncthreads();
        if (l < cn) cls[g][l] = g_ell[i * ELLW + l];
        if (l == 0) sdup[g] = 0;
        __syncthreads();
        bool dup = false;
        if (l < cn) {
            int v = cls[g][l];
            for (int s = 0; s < l; s++) if (cls[g][s] == v) { dup = true; break; }
        }
        if (dup) sdup[g] = 1;
        __syncthreads();
        if (l == 0) {
            if (sdup[g]) {
                int w = 0;
                for (int k = 0; k < cn; k++) {
                    int v = cls[g][k];
                    bool d = false;
                    for (int s = 0; s < w; s++) if (cls[g][s] == v) { d = true; break; }
                    if (!d) cls[g][w++] = v;
                }
                scn[g] = w;
            } else scn[g] = cn;
        }
        __syncthreads();
        int n = scn[g];
        float asx = 0.f, asy = 0.f, axx = 0.f, axy = 0.f;
        int k = 0;
        for (; k + 2 <= n; k += 2) {
            int j0 = cls[g][k], j1 = cls[g][k + 1];
            float2 e0 = *(const float2*)&g_E1[j0 * P1n + 2 * l];
            float2 e1 = *(const float2*)&g_E1[j1 * P1n + 2 * l];
            asx += e0.x + e1.x; asy += e0.y + e1.y;
            if (l < 32) {
                float2 a0 = *(const float2*)&g_XW1[j0 * Dd + 2 * l];
                float2 a1 = *(const float2*)&g_XW1[j1 * Dd + 2 * l];
                axx += a0.x + a1.x; axy += a0.y + a1.y;
            }
        }
        if (k < n) {
            int j0 = cls[g][k];
            float2 e0 = *(const float2*)&g_E1[j0 * P1n + 2 * l];
            asx += e0.x; asy += e0.y;
            if (l < 32) {
                float2 a0 = *(const float2*)&g_XW1[j0 * Dd + 2 * l];
                axx += a0.x; axy += a0.y;
            }
        }
        *(float2*)&g_AS1[i * P1n + 2 * l] = make_float2(asx, asy);
        if (l < 32) *(float2*)&g_ze1[i * Dd + 2 * l] = make_float2(tanhf(axx), tanhf(axy));
    }
}

// ---------------- split-K column GEMM halves: out = E1^T B ----------------
// grid 192 = 96 ksplits x 2 column halves of 32
template <int MODE>
__global__ void __launch_bounds__(256) colgemm(const float* __restrict__ yin) {
    int ks = blockIdx.x % 96, half = blockIdx.x / 96;
    int d0 = half * 32;
    const int chunk = 53;
    int rbeg = ks * chunk;
    int rend = rbeg + chunk; if (rend > Nn) rend = Nn;
    int tid = threadIdx.x;
    __shared__ float Ssh[8][P1n];
    __shared__ __align__(16) float Bsh[8][32];
    __shared__ float ysh[8];
    const float* __restrict__ B = (MODE == 0) ? g_ze1 : g_U;
    u64 acc2[16];
#pragma unroll
    for (int d = 0; d < 16; d++) acc2[d] = 0ull;
    float accY = 0.f;
    for (int t0 = rbeg; t0 < rend; t0 += 8) {
        __syncthreads();
#pragma unroll
        for (int lr = 0; lr < 8; lr++) {
            int row = t0 + lr;
            Ssh[lr][tid] = (row < rend) ? g_E1[row * P1n + tid] : 0.f;
        }
        if (tid < 64) {
            int lr = tid >> 3, q = tid & 7;
            int row = t0 + lr;
            float4 v = make_float4(0.f, 0.f, 0.f, 0.f);
            if (row < rend) v = *(const float4*)&B[row * Dd + d0 + q * 4];
            *(float4*)&Bsh[lr][q * 4] = v;
        }
        if (MODE == 0 && half == 0 && tid < 8) {
            int row = t0 + tid;
            ysh[tid] = (row < rend) ? yin[row] : 0.f;
        }
        __syncthreads();
#pragma unroll
        for (int r = 0; r < 8; r++) {
            float a = Ssh[r][tid];
            u64 ap = pk2(a, a);
            if (MODE == 0 && half == 0) accY += a * ysh[r];
            const ulonglong2* bb = (const ulonglong2*)&Bsh[r][0];
#pragma unroll
            for (int q = 0; q < 8; q++) {
                ulonglong2 bv = bb[q];
                fma2(acc2[2 * q], bv.x, ap);
                fma2(acc2[2 * q + 1], bv.y, ap);
            }
        }
    }
    if (MODE == 0) {
        const float m = g_invZ[tid] * M1;
#pragma unroll
        for (int qq = 0; qq < 8; qq++) {
            float a, b, c, d;
            unpk(acc2[2 * qq], a, b);
            unpk(acc2[2 * qq + 1], c, d);
            red4(&g_x1[tid * Dd + d0 + 4 * qq], a * m, b * m, c * m, d * m);
        }
        if (half == 0) atomicAdd(&g_y1[tid], accY * m);
    } else {
#pragma unroll
        for (int qq = 0; qq < 8; qq++) {
            float a, b, c, d;
            unpk(acc2[2 * qq], a, b);
            unpk(acc2[2 * qq + 1], c, d);
            red4(&g_V[tid * Dd + d0 + 4 * qq], a, b, c, d);
        }
    }
}

// ---------------- level-2: softmax2/S2 (blocks 0..31) + U = AS1 @ (D_iz x1) (32..110) ----------------
__global__ void __launch_bounds__(256) lvl2(const float* __restrict__ Wp2) {
    int b = blockIdx.x;
    int tid = threadIdx.x;
    if (b < P2n) {
        __shared__ float wcol[Dd];
        __shared__ float shE[8], shEV[8];
        __shared__ float sZ;
        if (tid < Dd) wcol[tid] = Wp2[tid * P2n + b];
        __syncthreads();
        float a = 0.f;
#pragma unroll
        for (int k = 0; k < Dd; k++) a += g_x1[tid * Dd + k] * wcol[k];
        float v = a * SCALE;
        float e = __expf(v);
        float se = e, sev = e * v;
#pragma unroll
        for (int off = 16; off; off >>= 1) {
            se += __shfl_down_sync(0xffffffffu, se, off);
            sev += __shfl_down_sync(0xffffffffu, sev, off);
        }
        if ((tid & 31) == 0) { shE[tid >> 5] = se; shEV[tid >> 5] = sev; }
        __syncthreads();
        if (tid == 0) {
            float Z = 0.f, EV = 0.f;
            for (int w = 0; w < 8; w++) { Z += shE[w]; EV += shEV[w]; }
            sZ = Z;
            atomicAdd(&g_acc[0], (__logf(Z) - EV / Z) * (1.f / ((float)P1n * (float)P2n)));
        }
        __syncthreads();
        g_S2[tid * P2n + b] = e / sZ;
        return;
    }
    int rb = (b - P2n) * 64;
    __shared__ __align__(16) float Xsh[32][Dd];
    __shared__ float Ash[64][33];
    int r = tid >> 2, cg = tid & 3;
    int c0 = cg * 16;
    u64 acc2[8];
#pragma unroll
    for (int q = 0; q < 8; q++) acc2[q] = 0ull;
    for (int kt = 0; kt < 8; kt++) {
        __syncthreads();
        for (int idx = tid; idx < 32 * Dd; idx += 256) {
            int kk = idx >> 6, j = idx & 63;
            Xsh[kk][j] = g_x1[(kt * 32 + kk) * Dd + j] * g_invZ[kt * 32 + kk];
        }
        for (int idx = tid; idx < 64 * 32; idx += 256) {
            int rr = idx >> 5, kk = idx & 31;
            int row = rb + rr;
            Ash[rr][kk] = (row < Nn) ? g_AS1[row * P1n + kt * 32 + kk] : 0.f;
        }
        __syncthreads();
#pragma unroll 4
        for (int kk = 0; kk < 32; kk++) {
            float a = Ash[r][kk];
            u64 ap = pk2(a, a);
            const u64* xs = (const u64*)&Xsh[kk][c0];
#pragma unroll
            for (int q = 0; q < 8; q++) fma2(acc2[q], xs[q], ap);
        }
    }
    int row = rb + r;
    if (row < Nn) {
#pragma unroll
        for (int q = 0; q < 4; q++) {
            float a, bb2, c, d;
            unpk(acc2[2 * q], a, bb2);
            unpk(acc2[2 * q + 1], c, d);
            *(float4*)&g_U[row * Dd + c0 + 4 * q] = make_float4(a, bb2, c, d);
        }
    }
}

// ---------------- ze2 = tanh((D_iz V) @ Wemb2), grid 16 ----------------
__global__ void __launch_bounds__(256) ze2k(const float* __restrict__ Wemb2) {
    int lb = blockIdx.x;
    int rb = (lb >> 2) * 64;
    int c0 = (lb & 3) * 16;
    int tid = threadIdx.x;
    __shared__ float Tsh[64][65];
    __shared__ __align__(16) float Wsh[64][16];
    for (int idx = tid; idx < 64 * 64; idx += 256) {
        int rr = idx >> 6, d = idx & 63;
        Tsh[rr][d] = g_V[(rb + rr) * Dd + d] * g_invZ[rb + rr];
    }
    for (int idx = tid; idx < 64 * 16; idx += 256) {
        int d = idx >> 4, c = idx & 15;
        Wsh[d][c] = Wemb2[d * Dd + c0 + c];
    }
    __syncthreads();
    int r = tid >> 2, cq = tid & 3;
    u64 acc2[2];
    acc2[0] = 0ull; acc2[1] = 0ull;
#pragma unroll 8
    for (int d = 0; d < 64; d++) {
        float a = Tsh[r][d];
        u64 ap = pk2(a, a);
        const u64* ws = (const u64*)&Wsh[d][cq * 4];
        fma2(acc2[0], ws[0], ap);
        fma2(acc2[1], ws[1], ap);
    }
    float a0, a1, a2, a3;
    unpk(acc2[0], a0, a1);
    unpk(acc2[1], a2, a3);
    float* dst = &g_ze2[(rb + r) * Dd + c0 + cq * 4];
    dst[0] = tanhf(a0); dst[1] = tanhf(a1); dst[2] = tanhf(a2); dst[3] = tanhf(a3);
}

// ---------------- decoder: PART 0 = z rows (625 blk), 1 = x1 rows (32), 2 = tail (4) ----------------
template <int PART>
__global__ void __launch_bounds__(256) decoderK(
    const float* __restrict__ W1, const float* __restrict__ W2,
    const float* __restrict__ b2, const float* __restrict__ yin) {
    int bb = blockIdx.x;
    int base = (PART == 0) ? bb * 8 : (PART == 1 ? Nn + bb * 8 : Nn + P1n + bb * 8);
    int h = threadIdx.x;
    __shared__ __align__(16) float zsh[8][Dd];
    __shared__ float ysh[8];
    __shared__ float2 sUR[8][8];
    __shared__ float pd[8], pr2[8];
    if (PART == 2) {
        const float scl = (float)P2n / (float)P1n;
        for (int idx = h; idx < 8 * Dd; idx += 256) {
            int r = idx >> 6, j = idx & 63;
            int p = base + r - (Nn + P1n);
            float a = 0.f;
            for (int k = 0; k < P1n; k++) a += g_S2[k * P2n + p] * g_ze2[k * Dd + j];
            zsh[r][j] = a * scl;
        }
        if (h < 8) {
            int p = base + h - (Nn + P1n);
            float a = 0.f;
            for (int k = 0; k < P1n; k++) a += g_S2[k * P2n + p] * g_y1[k];
            ysh[h] = a * scl;
        }
    } else {
        const float* src = (PART == 0) ? &g_z[base * Dd] : &g_x1[(base - Nn) * Dd];
        for (int idx = h; idx < 8 * Dd; idx += 256) zsh[idx >> 6][idx & 63] = src[idx];
        if (h < 8) ysh[h] = (PART == 0) ? yin[base + h] : g_y1[base + h - Nn];
    }
    __syncthreads();
    float c = g_c[h];
    u64 acc2[8];
#pragma unroll
    for (int r = 0; r < 8; r++) acc2[r] = 0ull;
#pragma unroll 8
    for (int jj = 0; jj < 32; jj++) {
        u64 wp = pk2(W1[(9 + 2 * jj) * Hh + h], W1[(10 + 2 * jj) * Hh + h]);
#pragma unroll
        for (int r = 0; r < 8; r++) {
            u64 zp = *(const u64*)&zsh[r][2 * jj];
            fma2(acc2[r], zp, wp);
        }
    }
    float w2 = W2[h], w0 = g_w0[h], q = g_q[h];
    int wid = h >> 5, lane = h & 31;
#pragma unroll
    for (int r = 0; r < 8; r++) {
        float a = c + sum2(acc2[r]);
        float th = tanhf(a);
        float s = 1.f - th * th;
        float up = w2 * th;
        float rp = w2 * s * (w0 + 2.f * th * q);
#pragma unroll
        for (int off = 16; off; off >>= 1) {
            up += __shfl_down_sync(0xffffffffu, up, off);
            rp += __shfl_down_sync(0xffffffffu, rp, off);
        }
        if (lane == 0) sUR[r][wid] = make_float2(up, rp);
    }
    __syncthreads();
    if (h < 8) {
        float u = b2[0], rr = 0.f;
        for (int w = 0; w < 8; w++) { float2 v = sUR[h][w]; u += v.x; rr += v.y; }
        float dd = u - ysh[h];
        pd[h] = dd * dd;
        pr2[h] = rr * rr;
    }
    __syncthreads();
    if (h == 0) {
        float s1 = 0.f, s2 = 0.f;
        for (int r = 0; r < 8; r++) { s1 += pd[r]; s2 += pr2[r]; }
        atomicAdd(&g_acc[1], s1);
        atomicAdd(&g_acc[2], s2);
    }
}

__global__ void fin(float* __restrict__ out) {
    out[0] = (g_acc[1] + g_acc[2]) * (1.f / (float)Mm) + g_acc[0];
}

// ---------------- launch: multi-branch graph via stream fork/join ----------------
extern "C" void kernel_launch(void* const* d_in, const int* in_sizes, int n_in,
                              void* d_out, int out_size) {
    const float* x0 = (const float*)d_in[0];
    const int* adj = (const int*)d_in[1];
    const float* t = (const float*)d_in[2];
    const float* y = (const float*)d_in[3];
    const float* Wenc = (const float*)d_in[4];
    const float* Wp1 = (const float*)d_in[5];
    const float* Wp2 = (const float*)d_in[6];
    const float* Wemb1 = (const float*)d_in[7];
    const float* Wemb2 = (const float*)d_in[8];
    const float* W1 = (const float*)d_in[9];
    const float* b1 = (const float*)d_in[10];
    const float* W2 = (const float*)d_in[11];
    const float* b2 = (const float*)d_in[12];
    float* out = (float*)d_out;

    // streams/events created once, on the (uncaptured) correctness call
    static cudaStream_t s1 = 0, s2 = 0;
    static cudaEvent_t evPrep = 0, evEdge = 0, evEnc = 0, evDecZ = 0, evX1 = 0, evT = 0;
    if (s1 == 0) {
        cudaStreamCreateWithFlags(&s1, cudaStreamNonBlocking);
        cudaStreamCreateWithFlags(&s2, cudaStreamNonBlocking);
        cudaEventCreateWithFlags(&evPrep, cudaEventDisableTiming);
        cudaEventCreateWithFlags(&evEdge, cudaEventDisableTiming);
        cudaEventCreateWithFlags(&evEnc, cudaEventDisableTiming);
        cudaEventCreateWithFlags(&evDecZ, cudaEventDisableTiming);
        cudaEventCreateWithFlags(&evX1, cudaEventDisableTiming);
        cudaEventCreateWithFlags(&evT, cudaEventDisableTiming);
    }

    prep<<<40, 256>>>(t, W1, b1);
    cudaEventRecord(evPrep, 0);

    // branch: edge scatter (needs g_cnt zeroed)
    cudaStreamWaitEvent(s1, evPrep, 0);
    edge_build<<<(Ee + 255) / 256, 256, 0, s1>>>(adj);
    cudaEventRecord(evEdge, s1);

    // main: encode
    encodeK<<<157, 256>>>(x0, Wenc, Wemb1, Wp1);
    cudaEventRecord(evEnc, 0);

    // branch: decoder over z-rows, concurrent with gather chain
    cudaStreamWaitEvent(s2, evEnc, 0);
    decoderK<0><<<625, 256, 0, s2>>>(W1, W2, b2, y);
    cudaEventRecord(evDecZ, s2);

    // main: gather (needs edges + encode) then x1/y1 pool
    cudaStreamWaitEvent(0, evEdge, 0);
    gather_fused<<<1251, 256>>>();
    colgemm<0><<<192, 256>>>(y);
    cudaEventRecord(evX1, 0);

    // branch: level-2 tail chain
    cudaStreamWaitEvent(s1, evX1, 0);
    lvl2<<<111, 256, 0, s1>>>(Wp2);
    colgemm<1><<<192, 256, 0, s1>>>(nullptr);
    ze2k<<<16, 256, 0, s1>>>(Wemb2);
    decoderK<2><<<4, 256, 0, s1>>>(W1, W2, b2, y);
    cudaEventRecord(evT, s1);

    // main: decoder over x1-rows (concurrent with tail chain)
    decoderK<1><<<32, 256>>>(W1, W2, b2, y);

    // join + final
    cudaStreamWaitEvent(0, evDecZ, 0);
    cudaStreamWaitEvent(0, evT, 0);
    fin<<<1, 1>>>(out);
}

// round 10
// speedup vs baseline: 1.0843x; 1.0843x over previous
#include <cuda_runtime.h>

#define Nn 5000
#define Ee 80000
#define FIN 32
#define Dd 64
#define P1n 256
#define P2n 32
#define Hh 256
#define Mm 5288
#define ELLW 64
#define SCALE 1.4763057f
#define M1 (256.f/5000.f)

typedef unsigned long long u64;

// ---------------- packed f32x2 helpers ----------------
__device__ __forceinline__ void fma2(u64& acc, u64 b, u64 a) {
    asm("fma.rn.f32x2 %0, %1, %2, %0;" : "+l"(acc) : "l"(b), "l"(a));
}
__device__ __forceinline__ u64 pk2(float lo, float hi) {
    u64 r; asm("mov.b64 %0, {%1, %2};" : "=l"(r) : "f"(lo), "f"(hi)); return r;
}
__device__ __forceinline__ void unpk(u64 v, float& a, float& b) {
    asm("mov.b64 {%0, %1}, %2;" : "=f"(a), "=f"(b) : "l"(v));
}
__device__ __forceinline__ float sum2(u64 v) {
    float a, b; unpk(v, a, b); return a + b;
}
__device__ __forceinline__ void red4(float* p, float a, float b, float c, float d) {
    asm volatile("red.global.add.v4.f32 [%0], {%1,%2,%3,%4};"
                 :: "l"(p), "f"(a), "f"(b), "f"(c), "f"(d) : "memory");
}

// ---------------- scratch (static, no allocation) ----------------
__device__ __align__(16) float g_z[Nn * Dd];
__device__ __align__(16) float g_XW1[Nn * Dd];
__device__ __align__(16) float g_E1[Nn * P1n];   // exp(P1) unnormalized
__device__ __align__(16) float g_AS1[Nn * P1n];  // A @ E1 (unscaled)
__device__ __align__(16) float g_ze1[Nn * Dd];
__device__ __align__(16) float g_U[5056 * Dd];   // AS1 @ (D_iz x1)
__device__ int g_cnt[Nn];
__device__ int g_ell[Nn * ELLW];
__device__ float g_colE[P1n], g_colEV[P1n], g_invZ[P1n];
__device__ __align__(16) float g_x1[P1n * Dd];
__device__ float g_y1[P1n];
__device__ __align__(16) float g_V[P1n * Dd];    // E1^T U (unscaled)
__device__ __align__(16) float g_S2[P1n * P2n];
__device__ __align__(16) float g_ze2[P1n * Dd];
__device__ float g_c[Hh], g_q[Hh], g_w0[Hh];
__device__ float g_acc[4];   // [0]=ent, [1]=sum(u-y)^2, [2]=sum(res^2)
__device__ unsigned int g_done;

// ---------------- kernel 1: zero accumulators + decoder prep ----------------
__global__ void prep(const float* __restrict__ t, const float* __restrict__ W1,
                     const float* __restrict__ b1) {
    int i = blockIdx.x * blockDim.x + threadIdx.x;
    int st = gridDim.x * blockDim.x;
    for (int k = i; k < Nn; k += st) g_cnt[k] = 0;
    for (int k = i; k < P1n; k += st) { g_colE[k] = 0.f; g_colEV[k] = 0.f; g_y1[k] = 0.f; }
    for (int k = i; k < P1n * Dd; k += st) { g_x1[k] = 0.f; g_V[k] = 0.f; }
    if (i == 0) { g_acc[0] = g_acc[1] = g_acc[2] = g_acc[3] = 0.f; g_done = 0u; }
    if (blockIdx.x == 0) {
        int h = threadIdx.x;
        float t0 = t[0];
        float tx[6];
        tx[0] = t0 * 1e-2f;
        tx[1] = t0 * 1e-3f;
        tx[2] = t0 * 1e-4f;
        tx[3] = logf(t0 * 100.f + 1.f);
        tx[4] = logf(t0 * 10.f + 1.f);
        tx[5] = logf(t0 + 1.f);
        float c = b1[h];
#pragma unroll
        for (int k = 0; k < 6; k++) c += W1[k * Hh + h] * tx[k];
        float q = 0.f;
#pragma unroll
        for (int k = 1; k < 9; k++) { float w = W1[k * Hh + h]; q += w * w; }
        g_c[h] = c; g_q[h] = q; g_w0[h] = W1[h];
    }
}

// ---------------- kernel 2: encode (blocks 0..156) + edge ELL scatter (blocks 157..469) ----------------
__global__ void __launch_bounds__(256) enc_edge(
    const float* __restrict__ x0, const float* __restrict__ Wenc,
    const float* __restrict__ Wemb, const float* __restrict__ Wp,
    const int* __restrict__ adj) {
    int tid = threadIdx.x;
    if (blockIdx.x >= 157) {
        int e = (blockIdx.x - 157) * 256 + tid;
        if (e < Ee) {
            int r0 = adj[e], r1 = adj[Ee + e];
            int pos = atomicAdd(&g_cnt[r0], 1);
            if (pos < ELLW) g_ell[r0 * ELLW + pos] = r1;
        }
        return;
    }
    __shared__ float xsh[32][FIN];
    __shared__ __align__(16) float zsh[32][Dd];
    int r0 = blockIdx.x * 32;
    for (int idx = tid; idx < 32 * FIN; idx += 256) {
        int r = idx / FIN, c = idx % FIN;
        int row = r0 + r;
        xsh[r][c] = (row < Nn) ? x0[row * FIN + c] : 0.f;
    }
    __syncthreads();
    for (int idx = tid; idx < 32 * Dd; idx += 256) {
        int r = idx / Dd, d = idx % Dd;
        float a = 0.f;
#pragma unroll
        for (int k = 0; k < FIN; k++) a += xsh[r][k] * Wenc[k * (Dd + 3) + d];
        float v = tanhf(a) * SCALE;
        zsh[r][d] = v;
        int row = r0 + r;
        if (row < Nn) g_z[row * Dd + d] = v;
    }
    __syncthreads();
    for (int idx = tid; idx < 32 * Dd; idx += 256) {
        int r = idx / Dd, d = idx % Dd;
        int row = r0 + r;
        if (row < Nn) {
            float a = 0.f;
#pragma unroll
            for (int k = 0; k < Dd; k++) a += zsh[r][k] * Wemb[k * Dd + d];
            g_XW1[row * Dd + d] = a;
        }
    }
    int p = tid;
    u64 wp[32];
#pragma unroll
    for (int kk = 0; kk < 32; kk++)
        wp[kk] = pk2(Wp[(2 * kk) * P1n + p], Wp[(2 * kk + 1) * P1n + p]);
    float se = 0.f, sev = 0.f;
    int rmax = Nn - r0; if (rmax > 32) rmax = 32;
    for (int r = 0; r < rmax; r++) {
        u64 acc = 0ull;
        const ulonglong2* zz = (const ulonglong2*)zsh[r];
#pragma unroll
        for (int q = 0; q < 16; q++) {
            ulonglong2 zp = zz[q];
            fma2(acc, zp.x, wp[2 * q]);
            fma2(acc, zp.y, wp[2 * q + 1]);
        }
        float v = sum2(acc) * SCALE;
        float e = __expf(v);
        g_E1[(r0 + r) * P1n + p] = e;
        se += e; sev += e * v;
    }
    atomicAdd(&g_colE[p], se);
    atomicAdd(&g_colEV[p], sev);
}

// ---------------- kernel 3: per-row dedup + sparse gathers + finalize ----------------
// blocks 0..1249: 4 row-slots of 64 threads, float4 loads
// block 1250: finalize invZ + level-1 entropy
__global__ void __launch_bounds__(256) gather_fused() {
    if (blockIdx.x == 1250) {
        int p = threadIdx.x;
        float Z = g_colE[p];
        float iz = 1.f / Z;
        g_invZ[p] = iz;
        float ent = __logf(Z) - g_colEV[p] * iz;
        __shared__ float sh[8];
#pragma unroll
        for (int off = 16; off; off >>= 1) ent += __shfl_down_sync(0xffffffffu, ent, off);
        if ((p & 31) == 0) sh[p >> 5] = ent;
        __syncthreads();
        if (p == 0) {
            float s = 0.f;
            for (int w = 0; w < 8; w++) s += sh[w];
            atomicAdd(&g_acc[0], s * (1.f / ((float)Nn * (float)P1n)));
        }
        return;
    }
    int s = threadIdx.x >> 6;      // row slot 0..3
    int l = threadIdx.x & 63;      // lane in slot
    int i = blockIdx.x * 4 + s;
    __shared__ int cls[4][ELLW];
    __shared__ int scn[4];
    __shared__ int sdup[4];
    int cn = g_cnt[i]; if (cn > ELLW) cn = ELLW;
    if (l < cn) cls[s][l] = g_ell[i * ELLW + l];
    if (l == 0) sdup[s] = 0;
    __syncthreads();
    bool dup = false;
    if (l < cn) {
        int v = cls[s][l];
        for (int k = 0; k < l; k++) if (cls[s][k] == v) { dup = true; break; }
    }
    if (dup) sdup[s] = 1;
    __syncthreads();
    if (l == 0) {
        if (sdup[s]) {  // rare: compact serially
            int w = 0;
            for (int k = 0; k < cn; k++) {
                int v = cls[s][k];
                bool d = false;
                for (int q = 0; q < w; q++) if (cls[s][q] == v) { d = true; break; }
                if (!d) cls[s][w++] = v;
            }
            scn[s] = w;
        } else scn[s] = cn;
    }
    __syncthreads();
    int n = scn[s];
    float4 as = make_float4(0.f, 0.f, 0.f, 0.f);
    float4 ax = make_float4(0.f, 0.f, 0.f, 0.f);
    int k = 0;
    for (; k + 2 <= n; k += 2) {
        int j0 = cls[s][k], j1 = cls[s][k + 1];
        float4 e0 = *(const float4*)&g_E1[j0 * P1n + 4 * l];
        float4 e1 = *(const float4*)&g_E1[j1 * P1n + 4 * l];
        as.x += e0.x + e1.x; as.y += e0.y + e1.y;
        as.z += e0.z + e1.z; as.w += e0.w + e1.w;
        if (l < 16) {
            float4 a0 = *(const float4*)&g_XW1[j0 * Dd + 4 * l];
            float4 a1 = *(const float4*)&g_XW1[j1 * Dd + 4 * l];
            ax.x += a0.x + a1.x; ax.y += a0.y + a1.y;
            ax.z += a0.z + a1.z; ax.w += a0.w + a1.w;
        }
    }
    if (k < n) {
        int j0 = cls[s][k];
        float4 e0 = *(const float4*)&g_E1[j0 * P1n + 4 * l];
        as.x += e0.x; as.y += e0.y; as.z += e0.z; as.w += e0.w;
        if (l < 16) {
            float4 a0 = *(const float4*)&g_XW1[j0 * Dd + 4 * l];
            ax.x += a0.x; ax.y += a0.y; ax.z += a0.z; ax.w += a0.w;
        }
    }
    *(float4*)&g_AS1[i * P1n + 4 * l] = as;
    if (l < 16)
        *(float4*)&g_ze1[i * Dd + 4 * l] =
            make_float4(tanhf(ax.x), tanhf(ax.y), tanhf(ax.z), tanhf(ax.w));
}

// ---------------- kernels 4/6: split-K column GEMM halves: out = E1^T B ----------------
// grid 192 = 96 ksplits x 2 column halves of 32
template <int MODE>
__global__ void __launch_bounds__(256) colgemm(const float* __restrict__ yin) {
    int ks = blockIdx.x % 96, half = blockIdx.x / 96;
    int d0 = half * 32;
    const int chunk = 53;
    int rbeg = ks * chunk;
    int rend = rbeg + chunk; if (rend > Nn) rend = Nn;
    int tid = threadIdx.x;
    __shared__ float Ssh[8][P1n];
    __shared__ __align__(16) float Bsh[8][32];
    __shared__ float ysh[8];
    const float* __restrict__ B = (MODE == 0) ? g_ze1 : g_U;
    u64 acc2[16];
#pragma unroll
    for (int d = 0; d < 16; d++) acc2[d] = 0ull;
    float accY = 0.f;
    for (int t0 = rbeg; t0 < rend; t0 += 8) {
        __syncthreads();
#pragma unroll
        for (int lr = 0; lr < 8; lr++) {
            int row = t0 + lr;
            Ssh[lr][tid] = (row < rend) ? g_E1[row * P1n + tid] : 0.f;
        }
        if (tid < 64) {
            int lr = tid >> 3, q = tid & 7;
            int row = t0 + lr;
            float4 v = make_float4(0.f, 0.f, 0.f, 0.f);
            if (row < rend) v = *(const float4*)&B[row * Dd + d0 + q * 4];
            *(float4*)&Bsh[lr][q * 4] = v;
        }
        if (MODE == 0 && half == 0 && tid < 8) {
            int row = t0 + tid;
            ysh[tid] = (row < rend) ? yin[row] : 0.f;
        }
        __syncthreads();
#pragma unroll
        for (int r = 0; r < 8; r++) {
            float a = Ssh[r][tid];
            u64 ap = pk2(a, a);
            if (MODE == 0 && half == 0) accY += a * ysh[r];
            const ulonglong2* bb = (const ulonglong2*)&Bsh[r][0];
#pragma unroll
            for (int q = 0; q < 8; q++) {
                ulonglong2 bv = bb[q];
                fma2(acc2[2 * q], bv.x, ap);
                fma2(acc2[2 * q + 1], bv.y, ap);
            }
        }
    }
    if (MODE == 0) {
        const float m = g_invZ[tid] * M1;
#pragma unroll
        for (int qq = 0; qq < 8; qq++) {
            float a, b, c, d;
            unpk(acc2[2 * qq], a, b);
            unpk(acc2[2 * qq + 1], c, d);
            red4(&g_x1[tid * Dd + d0 + 4 * qq], a * m, b * m, c * m, d * m);
        }
        if (half == 0) atomicAdd(&g_y1[tid], accY * m);
    } else {
#pragma unroll
        for (int qq = 0; qq < 8; qq++) {
            float a, b, c, d;
            unpk(acc2[2 * qq], a, b);
            unpk(acc2[2 * qq + 1], c, d);
            red4(&g_V[tid * Dd + d0 + 4 * qq], a, b, c, d);
        }
    }
}

// ---------------- kernel 5: softmax2/S2 (blocks 0..31) + U = AS1 @ (D_iz x1) (32..110) ----------------
__global__ void __launch_bounds__(256) lvl2(const float* __restrict__ Wp2) {
    int b = blockIdx.x;
    int tid = threadIdx.x;
    if (b < P2n) {
        __shared__ float wcol[Dd];
        __shared__ float shE[8], shEV[8];
        __shared__ float sZ;
        if (tid < Dd) wcol[tid] = Wp2[tid * P2n + b];
        __syncthreads();
        float a = 0.f;
#pragma unroll
        for (int k = 0; k < Dd; k++) a += g_x1[tid * Dd + k] * wcol[k];
        float v = a * SCALE;
        float e = __expf(v);
        float se = e, sev = e * v;
#pragma unroll
        for (int off = 16; off; off >>= 1) {
            se += __shfl_down_sync(0xffffffffu, se, off);
            sev += __shfl_down_sync(0xffffffffu, sev, off);
        }
        if ((tid & 31) == 0) { shE[tid >> 5] = se; shEV[tid >> 5] = sev; }
        __syncthreads();
        if (tid == 0) {
            float Z = 0.f, EV = 0.f;
            for (int w = 0; w < 8; w++) { Z += shE[w]; EV += shEV[w]; }
            sZ = Z;
            atomicAdd(&g_acc[0], (__logf(Z) - EV / Z) * (1.f / ((float)P1n * (float)P2n)));
        }
        __syncthreads();
        g_S2[tid * P2n + b] = e / sZ;
        return;
    }
    int rb = (b - P2n) * 64;
    __shared__ __align__(16) float Xsh[32][Dd];
    __shared__ float Ash[64][33];
    int r = tid >> 2, cg = tid & 3;
    int c0 = cg * 16;
    u64 acc2[8];
#pragma unroll
    for (int q = 0; q < 8; q++) acc2[q] = 0ull;
    for (int kt = 0; kt < 8; kt++) {
        __syncthreads();
        for (int idx = tid; idx < 32 * Dd; idx += 256) {
            int kk = idx >> 6, j = idx & 63;
            Xsh[kk][j] = g_x1[(kt * 32 + kk) * Dd + j] * g_invZ[kt * 32 + kk];
        }
        for (int idx = tid; idx < 64 * 32; idx += 256) {
            int rr = idx >> 5, kk = idx & 31;
            int row = rb + rr;
            Ash[rr][kk] = (row < Nn) ? g_AS1[row * P1n + kt * 32 + kk] : 0.f;
        }
        __syncthreads();
#pragma unroll 4
        for (int kk = 0; kk < 32; kk++) {
            float a = Ash[r][kk];
            u64 ap = pk2(a, a);
            const u64* xs = (const u64*)&Xsh[kk][c0];
#pragma unroll
            for (int q = 0; q < 8; q++) fma2(acc2[q], xs[q], ap);
        }
    }
    int row = rb + r;
    if (row < Nn) {
#pragma unroll
        for (int q = 0; q < 4; q++) {
            float a, bb2, c, d;
            unpk(acc2[2 * q], a, bb2);
            unpk(acc2[2 * q + 1], c, d);
            *(float4*)&g_U[row * Dd + c0 + 4 * q] = make_float4(a, bb2, c, d);
        }
    }
}

// ---------------- kernel 7: ze2 = tanh((D_iz V) @ Wemb2), grid 16 ----------------
__global__ void __launch_bounds__(256) ze2k(const float* __restrict__ Wemb2) {
    int lb = blockIdx.x;
    int rb = (lb >> 2) * 64;
    int c0 = (lb & 3) * 16;
    int tid = threadIdx.x;
    __shared__ float Tsh[64][65];
    __shared__ __align__(16) float Wsh[64][16];
    for (int idx = tid; idx < 64 * 64; idx += 256) {
        int rr = idx >> 6, d = idx & 63;
        Tsh[rr][d] = g_V[(rb + rr) * Dd + d] * g_invZ[rb + rr];
    }
    for (int idx = tid; idx < 64 * 16; idx += 256) {
        int d = idx >> 4, c = idx & 15;
        Wsh[d][c] = Wemb2[d * Dd + c0 + c];
    }
    __syncthreads();
    int r = tid >> 2, cq = tid & 3;
    u64 acc2[2];
    acc2[0] = 0ull; acc2[1] = 0ull;
#pragma unroll 8
    for (int d = 0; d < 64; d++) {
        float a = Tsh[r][d];
        u64 ap = pk2(a, a);
        const u64* ws = (const u64*)&Wsh[d][cq * 4];
        fma2(acc2[0], ws[0], ap);
        fma2(acc2[1], ws[1], ap);
    }
    float a0, a1, a2, a3;
    unpk(acc2[0], a0, a1);
    unpk(acc2[1], a2, a3);
    float* dst = &g_ze2[(rb + r) * Dd + c0 + cq * 4];
    dst[0] = tanhf(a0); dst[1] = tanhf(a1); dst[2] = tanhf(a2); dst[3] = tanhf(a3);
}

// ---------------- kernel 8: decoder + losses + inline pool2 + final reduce ----------------
// blocks 0..3: tail rows (pool2 inline); blocks 4..660: z/x1 rows
__global__ void __launch_bounds__(256) decoder(
    const float* __restrict__ W1, const float* __restrict__ W2,
    const float* __restrict__ b2, const float* __restrict__ yin,
    float* __restrict__ out) {
    int bb = blockIdx.x;
    bool tail = (bb < 4);
    int base = tail ? (Nn + P1n + bb * 8) : (bb - 4) * 8;
    int h = threadIdx.x;
    __shared__ __align__(16) float zsh[8][Dd];
    __shared__ float ysh[8];
    __shared__ float2 sUR[8][8];
    __shared__ float pd[8], pr2[8];
    if (tail) {
        const float scl = (float)P2n / (float)P1n;
        for (int idx = h; idx < 8 * Dd; idx += 256) {
            int r = idx >> 6, j = idx & 63;
            int p = base + r - (Nn + P1n);
            float a = 0.f;
            for (int k = 0; k < P1n; k++) a += g_S2[k * P2n + p] * g_ze2[k * Dd + j];
            zsh[r][j] = a * scl;
        }
        if (h < 8) {
            int p = base + h - (Nn + P1n);
            float a = 0.f;
            for (int k = 0; k < P1n; k++) a += g_S2[k * P2n + p] * g_y1[k];
            ysh[h] = a * scl;
        }
    } else {
        for (int idx = h; idx < 8 * Dd; idx += 256) {
            int r = idx >> 6, j = idx & 63;
            int m = base + r;
            zsh[r][j] = (m < Nn) ? g_z[m * Dd + j] : g_x1[(m - Nn) * Dd + j];
        }
        if (h < 8) {
            int m = base + h;
            ysh[h] = (m < Nn) ? yin[m] : g_y1[m - Nn];
        }
    }
    __syncthreads();
    float c = g_c[h];
    u64 acc2[8];
#pragma unroll
    for (int r = 0; r < 8; r++) acc2[r] = 0ull;
#pragma unroll 8
    for (int jj = 0; jj < 32; jj++) {
        u64 wp = pk2(W1[(9 + 2 * jj) * Hh + h], W1[(10 + 2 * jj) * Hh + h]);
#pragma unroll
        for (int r = 0; r < 8; r++) {
            u64 zp = *(const u64*)&zsh[r][2 * jj];
            fma2(acc2[r], zp, wp);
        }
    }
    float w2 = W2[h], w0 = g_w0[h], q = g_q[h];
    int wid = h >> 5, lane = h & 31;
#pragma unroll
    for (int r = 0; r < 8; r++) {
        float a = c + sum2(acc2[r]);
        float th = tanhf(a);
        float s = 1.f - th * th;
        float up = w2 * th;
        float rp = w2 * s * (w0 + 2.f * th * q);
#pragma unroll
        for (int off = 16; off; off >>= 1) {
            up += __shfl_down_sync(0xffffffffu, up, off);
            rp += __shfl_down_sync(0xffffffffu, rp, off);
        }
        if (lane == 0) sUR[r][wid] = make_float2(up, rp);
    }
    __syncthreads();
    if (h < 8) {
        float u = b2[0], rr = 0.f;
        for (int w = 0; w < 8; w++) { float2 v = sUR[h][w]; u += v.x; rr += v.y; }
        float dd = u - ysh[h];
        pd[h] = dd * dd;
        pr2[h] = rr * rr;
    }
    __syncthreads();
    if (h == 0) {
        float s1 = 0.f, s2 = 0.f;
        for (int r = 0; r < 8; r++) { s1 += pd[r]; s2 += pr2[r]; }
        atomicAdd(&g_acc[1], s1);
        atomicAdd(&g_acc[2], s2);
        __threadfence();
        unsigned int old = atomicAdd(&g_done, 1u);
        if (old == 660u) {
            float a0 = *(volatile float*)&g_acc[0];
            float a1 = *(volatile float*)&g_acc[1];
            float a2 = *(volatile float*)&g_acc[2];
            out[0] = (a1 + a2) * (1.f / (float)Mm) + a0;
        }
    }
}

// ---------------- launch: 8 serial nodes ----------------
extern "C" void kernel_launch(void* const* d_in, const int* in_sizes, int n_in,
                              void* d_out, int out_size) {
    const float* x0 = (const float*)d_in[0];
    const int* adj = (const int*)d_in[1];
    const float* t = (const float*)d_in[2];
    const float* y = (const float*)d_in[3];
    const float* Wenc = (const float*)d_in[4];
    const float* Wp1 = (const float*)d_in[5];
    const float* Wp2 = (const float*)d_in[6];
    const float* Wemb1 = (const float*)d_in[7];
    const float* Wemb2 = (const float*)d_in[8];
    const float* W1 = (const float*)d_in[9];
    const float* b1 = (const float*)d_in[10];
    const float* W2 = (const float*)d_in[11];
    const float* b2 = (const float*)d_in[12];
    float* out = (float*)d_out;

    prep<<<40, 256>>>(t, W1, b1);
    enc_edge<<<470, 256>>>(x0, Wenc, Wemb1, Wp1, adj);
    gather_fused<<<1251, 256>>>();
    colgemm<0><<<192, 256>>>(y);
    lvl2<<<111, 256>>>(Wp2);
    colgemm<1><<<192, 256>>>(nullptr);
    ze2k<<<16, 256>>>(Wemb2);
    decoder<<<661, 256>>>(W1, W2, b2, y, out);
}

// round 11
// speedup vs baseline: 1.0913x; 1.0064x over previous
#include <cuda_runtime.h>

#define Nn 5000
#define Ee 80000
#define FIN 32
#define Dd 64
#define P1n 256
#define P2n 32
#define Hh 256
#define Mm 5288
#define ELLW 64
#define SCALE 1.4763057f
#define M1 (256.f/5000.f)
#define KSPLIT 192
#define CHUNK 27

typedef unsigned long long u64;

// ---------------- packed f32x2 helpers ----------------
__device__ __forceinline__ void fma2(u64& acc, u64 b, u64 a) {
    asm("fma.rn.f32x2 %0, %1, %2, %0;" : "+l"(acc) : "l"(b), "l"(a));
}
__device__ __forceinline__ u64 pk2(float lo, float hi) {
    u64 r; asm("mov.b64 %0, {%1, %2};" : "=l"(r) : "f"(lo), "f"(hi)); return r;
}
__device__ __forceinline__ void unpk(u64 v, float& a, float& b) {
    asm("mov.b64 {%0, %1}, %2;" : "=f"(a), "=f"(b) : "l"(v));
}
__device__ __forceinline__ float sum2(u64 v) {
    float a, b; unpk(v, a, b); return a + b;
}
__device__ __forceinline__ void red4(float* p, float a, float b, float c, float d) {
    asm volatile("red.global.add.v4.f32 [%0], {%1,%2,%3,%4};"
                 :: "l"(p), "f"(a), "f"(b), "f"(c), "f"(d) : "memory");
}

// ---------------- scratch (static, no allocation) ----------------
__device__ __align__(16) float g_z[Nn * Dd];
__device__ __align__(16) float g_XW1[Nn * Dd];
__device__ __align__(16) float g_E1[Nn * P1n];   // exp(P1) unnormalized
__device__ __align__(16) float g_AS1[Nn * P1n];  // A @ E1 (unscaled)
__device__ __align__(16) float g_ze1[Nn * Dd];
__device__ __align__(16) float g_U[5056 * Dd];   // AS1 @ (D_iz x1)
__device__ int g_cnt[Nn];
__device__ int g_ell[Nn * ELLW];
__device__ float g_colE[P1n], g_colEV[P1n], g_invZ[P1n];
__device__ __align__(16) float g_x1[P1n * Dd];
__device__ float g_y1[P1n];
__device__ __align__(16) float g_V[P1n * Dd];    // E1^T U (unscaled)
__device__ __align__(16) float g_S2[P1n * P2n];
__device__ __align__(16) float g_ze2[P1n * Dd];
__device__ float g_c[Hh], g_q[Hh], g_w0[Hh];
__device__ float g_acc[4];   // [0]=ent, [1]=sum(u-y)^2, [2]=sum(res^2)
__device__ unsigned int g_done;

// ---------------- kernel 1: zero accumulators + decoder prep ----------------
__global__ void prep(const float* __restrict__ t, const float* __restrict__ W1,
                     const float* __restrict__ b1) {
    int i = blockIdx.x * blockDim.x + threadIdx.x;
    int st = gridDim.x * blockDim.x;
    for (int k = i; k < Nn; k += st) g_cnt[k] = 0;
    for (int k = i; k < P1n; k += st) { g_colE[k] = 0.f; g_colEV[k] = 0.f; g_y1[k] = 0.f; }
    for (int k = i; k < P1n * Dd; k += st) { g_x1[k] = 0.f; g_V[k] = 0.f; }
    if (i == 0) { g_acc[0] = g_acc[1] = g_acc[2] = g_acc[3] = 0.f; g_done = 0u; }
    if (blockIdx.x == 0) {
        int h = threadIdx.x;
        float t0 = t[0];
        float tx[6];
        tx[0] = t0 * 1e-2f;
        tx[1] = t0 * 1e-3f;
        tx[2] = t0 * 1e-4f;
        tx[3] = logf(t0 * 100.f + 1.f);
        tx[4] = logf(t0 * 10.f + 1.f);
        tx[5] = logf(t0 + 1.f);
        float c = b1[h];
#pragma unroll
        for (int k = 0; k < 6; k++) c += W1[k * Hh + h] * tx[k];
        float q = 0.f;
#pragma unroll
        for (int k = 1; k < 9; k++) { float w = W1[k * Hh + h]; q += w * w; }
        g_c[h] = c; g_q[h] = q; g_w0[h] = W1[h];
    }
}

// ---------------- kernel 2: encode (blocks 0..156) + edge ELL scatter (blocks 157..469) ----------------
__global__ void __launch_bounds__(256) enc_edge(
    const float* __restrict__ x0, const float* __restrict__ Wenc,
    const float* __restrict__ Wemb, const float* __restrict__ Wp,
    const int* __restrict__ adj) {
    int tid = threadIdx.x;
    if (blockIdx.x >= 157) {
        int e = (blockIdx.x - 157) * 256 + tid;
        if (e < Ee) {
            int r0 = adj[e], r1 = adj[Ee + e];
            int pos = atomicAdd(&g_cnt[r0], 1);
            if (pos < ELLW) g_ell[r0 * ELLW + pos] = r1;
        }
        return;
    }
    __shared__ float xsh[32][FIN];
    __shared__ __align__(16) float zsh[32][Dd];
    int r0 = blockIdx.x * 32;
    for (int idx = tid; idx < 32 * FIN; idx += 256) {
        int r = idx / FIN, c = idx % FIN;
        int row = r0 + r;
        xsh[r][c] = (row < Nn) ? x0[row * FIN + c] : 0.f;
    }
    __syncthreads();
    for (int idx = tid; idx < 32 * Dd; idx += 256) {
        int r = idx / Dd, d = idx % Dd;
        float a = 0.f;
#pragma unroll
        for (int k = 0; k < FIN; k++) a += xsh[r][k] * Wenc[k * (Dd + 3) + d];
        float v = tanhf(a) * SCALE;
        zsh[r][d] = v;
        int row = r0 + r;
        if (row < Nn) g_z[row * Dd + d] = v;
    }
    __syncthreads();
    for (int idx = tid; idx < 32 * Dd; idx += 256) {
        int r = idx / Dd, d = idx % Dd;
        int row = r0 + r;
        if (row < Nn) {
            float a = 0.f;
#pragma unroll
            for (int k = 0; k < Dd; k++) a += zsh[r][k] * Wemb[k * Dd + d];
            g_XW1[row * Dd + d] = a;
        }
    }
    int p = tid;
    u64 wp[32];
#pragma unroll
    for (int kk = 0; kk < 32; kk++)
        wp[kk] = pk2(Wp[(2 * kk) * P1n + p], Wp[(2 * kk + 1) * P1n + p]);
    float se = 0.f, sev = 0.f;
    int rmax = Nn - r0; if (rmax > 32) rmax = 32;
    for (int r = 0; r < rmax; r++) {
        u64 acc = 0ull;
        const ulonglong2* zz = (const ulonglong2*)zsh[r];
#pragma unroll
        for (int q = 0; q < 16; q++) {
            ulonglong2 zp = zz[q];
            fma2(acc, zp.x, wp[2 * q]);
            fma2(acc, zp.y, wp[2 * q + 1]);
        }
        float v = sum2(acc) * SCALE;
        float e = __expf(v);
        g_E1[(r0 + r) * P1n + p] = e;
        se += e; sev += e * v;
    }
    atomicAdd(&g_colE[p], se);
    atomicAdd(&g_colEV[p], sev);
}

// ---------------- kernel 3: per-row dedup + sparse gathers + finalize ----------------
__global__ void __launch_bounds__(256) gather_fused() {
    if (blockIdx.x == 1250) {
        int p = threadIdx.x;
        float Z = g_colE[p];
        float iz = 1.f / Z;
        g_invZ[p] = iz;
        float ent = __logf(Z) - g_colEV[p] * iz;
        __shared__ float sh[8];
#pragma unroll
        for (int off = 16; off; off >>= 1) ent += __shfl_down_sync(0xffffffffu, ent, off);
        if ((p & 31) == 0) sh[p >> 5] = ent;
        __syncthreads();
        if (p == 0) {
            float s = 0.f;
            for (int w = 0; w < 8; w++) s += sh[w];
            atomicAdd(&g_acc[0], s * (1.f / ((float)Nn * (float)P1n)));
        }
        return;
    }
    int s = threadIdx.x >> 6;      // row slot 0..3
    int l = threadIdx.x & 63;      // lane in slot
    int i = blockIdx.x * 4 + s;
    __shared__ int cls[4][ELLW];
    __shared__ int scn[4];
    __shared__ int sdup[4];
    int cn = g_cnt[i]; if (cn > ELLW) cn = ELLW;
    if (l < cn) cls[s][l] = g_ell[i * ELLW + l];
    if (l == 0) sdup[s] = 0;
    __syncthreads();
    bool dup = false;
    if (l < cn) {
        int v = cls[s][l];
        for (int k = 0; k < l; k++) if (cls[s][k] == v) { dup = true; break; }
    }
    if (dup) sdup[s] = 1;
    __syncthreads();
    if (l == 0) {
        if (sdup[s]) {
            int w = 0;
            for (int k = 0; k < cn; k++) {
                int v = cls[s][k];
                bool d = false;
                for (int q = 0; q < w; q++) if (cls[s][q] == v) { d = true; break; }
                if (!d) cls[s][w++] = v;
            }
            scn[s] = w;
        } else scn[s] = cn;
    }
    __syncthreads();
    int n = scn[s];
    float4 as = make_float4(0.f, 0.f, 0.f, 0.f);
    float4 ax = make_float4(0.f, 0.f, 0.f, 0.f);
    int k = 0;
    for (; k + 2 <= n; k += 2) {
        int j0 = cls[s][k], j1 = cls[s][k + 1];
        float4 e0 = *(const float4*)&g_E1[j0 * P1n + 4 * l];
        float4 e1 = *(const float4*)&g_E1[j1 * P1n + 4 * l];
        as.x += e0.x + e1.x; as.y += e0.y + e1.y;
        as.z += e0.z + e1.z; as.w += e0.w + e1.w;
        if (l < 16) {
            float4 a0 = *(const float4*)&g_XW1[j0 * Dd + 4 * l];
            float4 a1 = *(const float4*)&g_XW1[j1 * Dd + 4 * l];
            ax.x += a0.x + a1.x; ax.y += a0.y + a1.y;
            ax.z += a0.z + a1.z; ax.w += a0.w + a1.w;
        }
    }
    if (k < n) {
        int j0 = cls[s][k];
        float4 e0 = *(const float4*)&g_E1[j0 * P1n + 4 * l];
        as.x += e0.x; as.y += e0.y; as.z += e0.z; as.w += e0.w;
        if (l < 16) {
            float4 a0 = *(const float4*)&g_XW1[j0 * Dd + 4 * l];
            ax.x += a0.x; ax.y += a0.y; ax.z += a0.z; ax.w += a0.w;
        }
    }
    *(float4*)&g_AS1[i * P1n + 4 * l] = as;
    if (l < 16)
        *(float4*)&g_ze1[i * Dd + 4 * l] =
            make_float4(tanhf(ax.x), tanhf(ax.y), tanhf(ax.z), tanhf(ax.w));
}

// ---------------- kernels 4/6: split-K column GEMM: out = E1^T B ----------------
// grid 384 = 192 ksplits x 2 column halves of 32. E1 read directly (coalesced LDG),
// only the tiny B chunk staged in smem, single sync.
template <int MODE>
__global__ void __launch_bounds__(256) colgemm(const float* __restrict__ yin) {
    int ks = blockIdx.x % KSPLIT, half = blockIdx.x / KSPLIT;
    int d0 = half * 32;
    int rbeg = ks * CHUNK;
    int rend = rbeg + CHUNK; if (rend > Nn) rend = Nn;
    int n = rend - rbeg; if (n <= 0) n = 0;
    int tid = threadIdx.x;
    __shared__ __align__(16) float Bsh[CHUNK][32];
    __shared__ float ysh[CHUNK];
    const float* __restrict__ B = (MODE == 0) ? g_ze1 : g_U;
    // stage B chunk (27 rows x 32 cols) with float4 loads
    for (int idx = tid; idx < CHUNK * 8; idx += 256) {
        int r = idx >> 3, q = idx & 7;
        float4 v = make_float4(0.f, 0.f, 0.f, 0.f);
        if (r < n) v = *(const float4*)&B[(rbeg + r) * Dd + d0 + q * 4];
        *(float4*)&Bsh[r][q * 4] = v;
    }
    if (MODE == 0 && half == 0 && tid < CHUNK)
        ysh[tid] = (tid < n) ? yin[rbeg + tid] : 0.f;
    __syncthreads();
    u64 acc2[16];
#pragma unroll
    for (int d = 0; d < 16; d++) acc2[d] = 0ull;
    float accY = 0.f;
    const float* __restrict__ ep = &g_E1[rbeg * P1n + tid];
    int r = 0;
    for (; r + 3 <= n; r += 3) {
        // batch 3 coalesced LDGs (MLP=3)
        float a0 = ep[0];
        float a1 = ep[P1n];
        float a2 = ep[2 * P1n];
        ep += 3 * P1n;
        u64 ap0 = pk2(a0, a0), ap1 = pk2(a1, a1), ap2 = pk2(a2, a2);
        if (MODE == 0 && half == 0)
            accY += a0 * ysh[r] + a1 * ysh[r + 1] + a2 * ysh[r + 2];
        const ulonglong2* b0 = (const ulonglong2*)&Bsh[r][0];
        const ulonglong2* b1 = (const ulonglong2*)&Bsh[r + 1][0];
        const ulonglong2* b2 = (const ulonglong2*)&Bsh[r + 2][0];
#pragma unroll
        for (int q = 0; q < 8; q++) {
            ulonglong2 v0 = b0[q];
            fma2(acc2[2 * q], v0.x, ap0);
            fma2(acc2[2 * q + 1], v0.y, ap0);
        }
#pragma unroll
        for (int q = 0; q < 8; q++) {
            ulonglong2 v1 = b1[q];
            fma2(acc2[2 * q], v1.x, ap1);
            fma2(acc2[2 * q + 1], v1.y, ap1);
        }
#pragma unroll
        for (int q = 0; q < 8; q++) {
            ulonglong2 v2 = b2[q];
            fma2(acc2[2 * q], v2.x, ap2);
            fma2(acc2[2 * q + 1], v2.y, ap2);
        }
    }
    for (; r < n; r++) {
        float a0 = ep[0]; ep += P1n;
        u64 ap0 = pk2(a0, a0);
        if (MODE == 0 && half == 0) accY += a0 * ysh[r];
        const ulonglong2* b0 = (const ulonglong2*)&Bsh[r][0];
#pragma unroll
        for (int q = 0; q < 8; q++) {
            ulonglong2 v0 = b0[q];
            fma2(acc2[2 * q], v0.x, ap0);
            fma2(acc2[2 * q + 1], v0.y, ap0);
        }
    }
    if (MODE == 0) {
        const float m = g_invZ[tid] * M1;
#pragma unroll
        for (int qq = 0; qq < 8; qq++) {
            float a, b, c, d;
            unpk(acc2[2 * qq], a, b);
            unpk(acc2[2 * qq + 1], c, d);
            red4(&g_x1[tid * Dd + d0 + 4 * qq], a * m, b * m, c * m, d * m);
        }
        if (half == 0) atomicAdd(&g_y1[tid], accY * m);
    } else {
#pragma unroll
        for (int qq = 0; qq < 8; qq++) {
            float a, b, c, d;
            unpk(acc2[2 * qq], a, b);
            unpk(acc2[2 * qq + 1], c, d);
            red4(&g_V[tid * Dd + d0 + 4 * qq], a, b, c, d);
        }
    }
}

// ---------------- kernel 5: softmax2/S2 (blocks 0..31) + U = AS1 @ (D_iz x1) (32..110) ----------------
__global__ void __launch_bounds__(256) lvl2(const float* __restrict__ Wp2) {
    int b = blockIdx.x;
    int tid = threadIdx.x;
    if (b < P2n) {
        __shared__ float wcol[Dd];
        __shared__ float shE[8], shEV[8];
        __shared__ float sZ;
        if (tid < Dd) wcol[tid] = Wp2[tid * P2n + b];
        __syncthreads();
        float a = 0.f;
#pragma unroll
        for (int k = 0; k < Dd; k++) a += g_x1[tid * Dd + k] * wcol[k];
        float v = a * SCALE;
        float e = __expf(v);
        float se = e, sev = e * v;
#pragma unroll
        for (int off = 16; off; off >>= 1) {
            se += __shfl_down_sync(0xffffffffu, se, off);
            sev += __shfl_down_sync(0xffffffffu, sev, off);
        }
        if ((tid & 31) == 0) { shE[tid >> 5] = se; shEV[tid >> 5] = sev; }
        __syncthreads();
        if (tid == 0) {
            float Z = 0.f, EV = 0.f;
            for (int w = 0; w < 8; w++) { Z += shE[w]; EV += shEV[w]; }
            sZ = Z;
            atomicAdd(&g_acc[0], (__logf(Z) - EV / Z) * (1.f / ((float)P1n * (float)P2n)));
        }
        __syncthreads();
        g_S2[tid * P2n + b] = e / sZ;
        return;
    }
    int rb = (b - P2n) * 64;
    __shared__ __align__(16) float Xsh[32][Dd];
    __shared__ float Ash[64][33];
    int r = tid >> 2, cg = tid & 3;
    int c0 = cg * 16;
    u64 acc2[8];
#pragma unroll
    for (int q = 0; q < 8; q++) acc2[q] = 0ull;
    for (int kt = 0; kt < 8; kt++) {
        __syncthreads();
        for (int idx = tid; idx < 32 * Dd; idx += 256) {
            int kk = idx >> 6, j = idx & 63;
            Xsh[kk][j] = g_x1[(kt * 32 + kk) * Dd + j] * g_invZ[kt * 32 + kk];
        }
        for (int idx = tid; idx < 64 * 32; idx += 256) {
            int rr = idx >> 5, kk = idx & 31;
            int row = rb + rr;
            Ash[rr][kk] = (row < Nn) ? g_AS1[row * P1n + kt * 32 + kk] : 0.f;
        }
        __syncthreads();
#pragma unroll 4
        for (int kk = 0; kk < 32; kk++) {
            float a = Ash[r][kk];
            u64 ap = pk2(a, a);
            const u64* xs = (const u64*)&Xsh[kk][c0];
#pragma unroll
            for (int q = 0; q < 8; q++) fma2(acc2[q], xs[q], ap);
        }
    }
    int row = rb + r;
    if (row < Nn) {
#pragma unroll
        for (int q = 0; q < 4; q++) {
            float a, bb2, c, d;
            unpk(acc2[2 * q], a, bb2);
            unpk(acc2[2 * q + 1], c, d);
            *(float4*)&g_U[row * Dd + c0 + 4 * q] = make_float4(a, bb2, c, d);
        }
    }
}

// ---------------- kernel 7: ze2 = tanh((D_iz V) @ Wemb2), grid 16 ----------------
__global__ void __launch_bounds__(256) ze2k(const float* __restrict__ Wemb2) {
    int lb = blockIdx.x;
    int rb = (lb >> 2) * 64;
    int c0 = (lb & 3) * 16;
    int tid = threadIdx.x;
    __shared__ float Tsh[64][65];
    __shared__ __align__(16) float Wsh[64][16];
    for (int idx = tid; idx < 64 * 64; idx += 256) {
        int rr = idx >> 6, d = idx & 63;
        Tsh[rr][d] = g_V[(rb + rr) * Dd + d] * g_invZ[rb + rr];
    }
    for (int idx = tid; idx < 64 * 16; idx += 256) {
        int d = idx >> 4, c = idx & 15;
        Wsh[d][c] = Wemb2[d * Dd + c0 + c];
    }
    __syncthreads();
    int r = tid >> 2, cq = tid & 3;
    u64 acc2[2];
    acc2[0] = 0ull; acc2[1] = 0ull;
#pragma unroll 8
    for (int d = 0; d < 64; d++) {
        float a = Tsh[r][d];
        u64 ap = pk2(a, a);
        const u64* ws = (const u64*)&Wsh[d][cq * 4];
        fma2(acc2[0], ws[0], ap);
        fma2(acc2[1], ws[1], ap);
    }
    float a0, a1, a2, a3;
    unpk(acc2[0], a0, a1);
    unpk(acc2[1], a2, a3);
    float* dst = &g_ze2[(rb + r) * Dd + c0 + cq * 4];
    dst[0] = tanhf(a0); dst[1] = tanhf(a1); dst[2] = tanhf(a2); dst[3] = tanhf(a3);
}

// ---------------- kernel 8: decoder + losses + inline pool2 + final reduce ----------------
__global__ void __launch_bounds__(256) decoder(
    const float* __restrict__ W1, const float* __restrict__ W2,
    const float* __restrict__ b2, const float* __restrict__ yin,
    float* __restrict__ out) {
    int bb = blockIdx.x;
    bool tail = (bb < 4);
    int base = tail ? (Nn + P1n + bb * 8) : (bb - 4) * 8;
    int h = threadIdx.x;
    __shared__ __align__(16) float zsh[8][Dd];
    __shared__ float ysh[8];
    __shared__ float2 sUR[8][8];
    __shared__ float pd[8], pr2[8];
    if (tail) {
        const float scl = (float)P2n / (float)P1n;
        for (int idx = h; idx < 8 * Dd; idx += 256) {
            int r = idx >> 6, j = idx & 63;
            int p = base + r - (Nn + P1n);
            float a = 0.f;
            for (int k = 0; k < P1n; k++) a += g_S2[k * P2n + p] * g_ze2[k * Dd + j];
            zsh[r][j] = a * scl;
        }
        if (h < 8) {
            int p = base + h - (Nn + P1n);
            float a = 0.f;
            for (int k = 0; k < P1n; k++) a += g_S2[k * P2n + p] * g_y1[k];
            ysh[h] = a * scl;
        }
    } else {
        for (int idx = h; idx < 8 * Dd; idx += 256) {
            int r = idx >> 6, j = idx & 63;
            int m = base + r;
            zsh[r][j] = (m < Nn) ? g_z[m * Dd + j] : g_x1[(m - Nn) * Dd + j];
        }
        if (h < 8) {
            int m = base + h;
            ysh[h] = (m < Nn) ? yin[m] : g_y1[m - Nn];
        }
    }
    __syncthreads();
    float c = g_c[h];
    u64 acc2[8];
#pragma unroll
    for (int r = 0; r < 8; r++) acc2[r] = 0ull;
#pragma unroll 8
    for (int jj = 0; jj < 32; jj++) {
        u64 wp = pk2(W1[(9 + 2 * jj) * Hh + h], W1[(10 + 2 * jj) * Hh + h]);
#pragma unroll
        for (int r = 0; r < 8; r++) {
            u64 zp = *(const u64*)&zsh[r][2 * jj];
            fma2(acc2[r], zp, wp);
        }
    }
    float w2 = W2[h], w0 = g_w0[h], q = g_q[h];
    int wid = h >> 5, lane = h & 31;
#pragma unroll
    for (int r = 0; r < 8; r++) {
        float a = c + sum2(acc2[r]);
        float th = tanhf(a);
        float s = 1.f - th * th;
        float up = w2 * th;
        float rp = w2 * s * (w0 + 2.f * th * q);
#pragma unroll
        for (int off = 16; off; off >>= 1) {
            up += __shfl_down_sync(0xffffffffu, up, off);
            rp += __shfl_down_sync(0xffffffffu, rp, off);
        }
        if (lane == 0) sUR[r][wid] = make_float2(up, rp);
    }
    __syncthreads();
    if (h < 8) {
        float u = b2[0], rr = 0.f;
        for (int w = 0; w < 8; w++) { float2 v = sUR[h][w]; u += v.x; rr += v.y; }
        float dd = u - ysh[h];
        pd[h] = dd * dd;
        pr2[h] = rr * rr;
    }
    __syncthreads();
    if (h == 0) {
        float s1 = 0.f, s2 = 0.f;
        for (int r = 0; r < 8; r++) { s1 += pd[r]; s2 += pr2[r]; }
        atomicAdd(&g_acc[1], s1);
        atomicAdd(&g_acc[2], s2);
        __threadfence();
        unsigned int old = atomicAdd(&g_done, 1u);
        if (old == 660u) {
            float a0 = *(volatile float*)&g_acc[0];
            float a1 = *(volatile float*)&g_acc[1];
            float a2 = *(volatile float*)&g_acc[2];
            out[0] = (a1 + a2) * (1.f / (float)Mm) + a0;
        }
    }
}

// ---------------- launch: 8 serial nodes ----------------
extern "C" void kernel_launch(void* const* d_in, const int* in_sizes, int n_in,
                              void* d_out, int out_size) {
    const float* x0 = (const float*)d_in[0];
    const int* adj = (const int*)d_in[1];
    const float* t = (const float*)d_in[2];
    const float* y = (const float*)d_in[3];
    const float* Wenc = (const float*)d_in[4];
    const float* Wp1 = (const float*)d_in[5];
    const float* Wp2 = (const float*)d_in[6];
    const float* Wemb1 = (const float*)d_in[7];
    const float* Wemb2 = (const float*)d_in[8];
    const float* W1 = (const float*)d_in[9];
    const float* b1 = (const float*)d_in[10];
    const float* W2 = (const float*)d_in[11];
    const float* b2 = (const float*)d_in[12];
    float* out = (float*)d_out;

    prep<<<40, 256>>>(t, W1, b1);
    enc_edge<<<470, 256>>>(x0, Wenc, Wemb1, Wp1, adj);
    gather_fused<<<1251, 256>>>();
    colgemm<0><<<2 * KSPLIT, 256>>>(y);
    lvl2<<<111, 256>>>(Wp2);
    colgemm<1><<<2 * KSPLIT, 256>>>(nullptr);
    ze2k<<<16, 256>>>(Wemb2);
    decoder<<<661, 256>>>(W1, W2, b2, y, out);
}